// round 1
// baseline (speedup 1.0000x reference)
#include <cuda_runtime.h>

#define S_DIM 100000
#define G_DIM 18000
#define H_DIM 256
#define E_DIM 600000
#define B_DIM 256

// Scratch (allocation-free: static __device__ globals)
__device__ float g_v[G_DIM];       // v[g] = sum_k W2[k] * W1[k,g]
__device__ float g_coef[S_DIM];    // coef[s] = sum_{e: snp==s} w_e * v[gene_e]
__device__ float g_const0;         // b2 + W2.b1 + v.gene_bias

// ---------------------------------------------------------------------------
__device__ __forceinline__ float block_reduce_sum(float v) {
    __shared__ float s[32];
    int lane = threadIdx.x & 31;
    int wid  = threadIdx.x >> 5;
    #pragma unroll
    for (int o = 16; o > 0; o >>= 1) v += __shfl_down_sync(0xffffffffu, v, o);
    if (lane == 0) s[wid] = v;
    __syncthreads();
    int nw = blockDim.x >> 5;
    v = (threadIdx.x < nw) ? s[threadIdx.x] : 0.0f;
    if (wid == 0) {
        #pragma unroll
        for (int o = 16; o > 0; o >>= 1) v += __shfl_down_sync(0xffffffffu, v, o);
    }
    return v;
}

// ---------------------------------------------------------------------------
// Kernel 1: v[g] = sum_k W1[k*G + g] * W2[k].  Coalesced column sweep of W1.
__global__ void k_build_v(const float* __restrict__ W1, const float* __restrict__ W2) {
    __shared__ float w2s[H_DIM];
    for (int i = threadIdx.x; i < H_DIM; i += blockDim.x) w2s[i] = W2[i];
    __syncthreads();
    int g = blockIdx.x * blockDim.x + threadIdx.x;
    if (g >= G_DIM) return;
    float acc = 0.0f;
    #pragma unroll 8
    for (int k = 0; k < H_DIM; k++)
        acc = fmaf(W1[(size_t)k * G_DIM + g], w2s[k], acc);
    g_v[g] = acc;
}

// ---------------------------------------------------------------------------
// Kernel 2: const0 = b2[0] + sum_k W2[k]*b1[k] + sum_g v[g]*gene_bias[g]
__global__ void k_const0(const float* __restrict__ b1, const float* __restrict__ W2,
                         const float* __restrict__ b2, const float* __restrict__ gene_bias) {
    float acc = W2[threadIdx.x] * b1[threadIdx.x];   // blockDim.x == H_DIM == 256
    for (int g = threadIdx.x; g < G_DIM; g += H_DIM)
        acc = fmaf(g_v[g], gene_bias[g], acc);
    float total = block_reduce_sum(acc);
    if (threadIdx.x == 0) g_const0 = total + b2[0];
}

// ---------------------------------------------------------------------------
// Kernel 3: zero coef, initialize out[b] = const0 (d_out is poisoned by harness)
__global__ void k_init(float* __restrict__ out) {
    int i = blockIdx.x * blockDim.x + threadIdx.x;
    if (i < S_DIM) g_coef[i] = 0.0f;
    if (i < B_DIM) out[i] = g_const0;
}

// ---------------------------------------------------------------------------
// Kernel 4: edge fold: coef[snp[e]] += w[e] * v[gene[e]]
__global__ void k_scatter(const int* __restrict__ snp, const int* __restrict__ gidx,
                          const float* __restrict__ ew) {
    int e = blockIdx.x * blockDim.x + threadIdx.x;
    if (e >= E_DIM) return;
    float val = ew[e] * g_v[gidx[e]];
    atomicAdd(&g_coef[snp[e]], val);
}

// ---------------------------------------------------------------------------
// Kernel 5: GEMV  out[b] += dot(x[b,:], coef)
// grid = (25 chunks of 4096 floats, 256 batch rows), 256 threads.
// Each thread handles 4 float4's; coef stays L2-resident (400 KB).
__global__ void k_gemv(const float* __restrict__ x, float* __restrict__ out) {
    const int chunk = blockIdx.x;      // 0..24
    const int b     = blockIdx.y;      // 0..255
    const float4* __restrict__ xr = reinterpret_cast<const float4*>(x + (size_t)b * S_DIM);
    const float4* __restrict__ cf = reinterpret_cast<const float4*>(g_coef);
    const int n4 = S_DIM / 4;          // 25000
    int i4 = chunk * 1024 + threadIdx.x;
    float acc = 0.0f;
    #pragma unroll
    for (int it = 0; it < 4; it++, i4 += 256) {
        if (i4 < n4) {
            float4 xv = xr[i4];
            float4 cv = cf[i4];
            acc += xv.x * cv.x + xv.y * cv.y + xv.z * cv.z + xv.w * cv.w;
        }
    }
    float total = block_reduce_sum(acc);
    if (threadIdx.x == 0) atomicAdd(&out[b], total);
}

// ---------------------------------------------------------------------------
extern "C" void kernel_launch(void* const* d_in, const int* in_sizes, int n_in,
                              void* d_out, int out_size) {
    const float* x    = (const float*)d_in[0];
    const int*   snp  = (const int*)  d_in[1];
    const int*   gidx = (const int*)  d_in[2];
    const float* ew   = (const float*)d_in[3];
    const float* gb   = (const float*)d_in[4];
    const float* W1   = (const float*)d_in[5];
    const float* b1   = (const float*)d_in[6];
    const float* W2   = (const float*)d_in[7];
    const float* b2   = (const float*)d_in[8];
    float* out = (float*)d_out;

    k_build_v<<<(G_DIM + 255) / 256, 256>>>(W1, W2);
    k_const0<<<1, H_DIM>>>(b1, W2, b2, gb);
    k_init<<<(S_DIM + 255) / 256, 256>>>(out);
    k_scatter<<<(E_DIM + 255) / 256, 256>>>(snp, gidx, ew);
    k_gemv<<<dim3(25, B_DIM), 256>>>(x, out);
}

// round 2
// speedup vs baseline: 1.4456x; 1.4456x over previous
#include <cuda_runtime.h>

#define S_DIM 100000
#define G_DIM 18000
#define H_DIM 256
#define E_DIM 600000
#define B_DIM 256

#define KT      8      // k-tiles in build_v (32 k's each)
#define CHUNKS  8      // gemv chunks along S
#define ROWS    8      // gemv rows per block
#define SCAT_BLOCKS 586   // ceil(150000/256)
#define C0_BLOCKS   9     // const0 tail blocks (2000 g's each)

__device__ float g_v[G_DIM];
__device__ float g_coef[S_DIM];
__device__ float g_const0;

// ---------------------------------------------------------------------------
// Kernel 1: zero all accumulators (coef, v, const0, out)
__global__ void k_prep(float* __restrict__ out) {
    int i = blockIdx.x * blockDim.x + threadIdx.x;
    if (i < S_DIM) g_coef[i] = 0.0f;
    if (i < G_DIM) g_v[i] = 0.0f;
    if (i < B_DIM) out[i] = 0.0f;
    if (i == 0)    g_const0 = 0.0f;
}

// ---------------------------------------------------------------------------
// Kernel 2: v[g] += sum over 32-k tile of W1[k,g]*W2[k].  grid=(71, KT)
__global__ void k_build_v(const float* __restrict__ W1, const float* __restrict__ W2) {
    __shared__ float w2s[32];
    const int k0 = blockIdx.y * (H_DIM / KT);
    if (threadIdx.x < 32) w2s[threadIdx.x] = W2[k0 + threadIdx.x];
    __syncthreads();
    int g = blockIdx.x * blockDim.x + threadIdx.x;
    if (g >= G_DIM) return;
    float acc = 0.0f;
    #pragma unroll
    for (int k = 0; k < 32; k++)
        acc = fmaf(W1[(size_t)(k0 + k) * G_DIM + g], w2s[k], acc);
    atomicAdd(&g_v[g], acc);
}

// ---------------------------------------------------------------------------
// Kernel 3: edge scatter (4 edges/thread, vectorized) + const0 tail blocks.
//   blocks [0, SCAT_BLOCKS):   coef[snp[e]] += w[e]*v[gene[e]]
//   blocks [SCAT_BLOCKS, +C0): g_const0 += partial( v.gene_bias ) (+ W2.b1 + b2)
__global__ void k_scatter(const int* __restrict__ snp, const int* __restrict__ gidx,
                          const float* __restrict__ ew,
                          const float* __restrict__ gene_bias,
                          const float* __restrict__ b1, const float* __restrict__ W2,
                          const float* __restrict__ b2) {
    if (blockIdx.x < SCAT_BLOCKS) {
        int i4 = blockIdx.x * blockDim.x + threadIdx.x;     // quad index
        if (i4 >= E_DIM / 4) return;
        int4   s4 = reinterpret_cast<const int4*>(snp)[i4];
        int4   g4 = reinterpret_cast<const int4*>(gidx)[i4];
        float4 w4 = reinterpret_cast<const float4*>(ew)[i4];
        float v0 = g_v[g4.x], v1 = g_v[g4.y], v2 = g_v[g4.z], v3 = g_v[g4.w];
        atomicAdd(&g_coef[s4.x], w4.x * v0);
        atomicAdd(&g_coef[s4.y], w4.y * v1);
        atomicAdd(&g_coef[s4.z], w4.z * v2);
        atomicAdd(&g_coef[s4.w], w4.w * v3);
        return;
    }
    // ---- const0 tail ----
    int local = blockIdx.x - SCAT_BLOCKS;                   // 0..8
    int start = local * (G_DIM / C0_BLOCKS);                // 2000 per block
    float acc = 0.0f;
    for (int g = start + threadIdx.x; g < start + G_DIM / C0_BLOCKS; g += blockDim.x)
        acc = fmaf(g_v[g], gene_bias[g], acc);
    if (local == 0) {
        acc = fmaf(W2[threadIdx.x], b1[threadIdx.x], acc);  // blockDim == H_DIM
        if (threadIdx.x == 0) acc += b2[0];
    }
    // block reduce
    __shared__ float sm[32];
    int lane = threadIdx.x & 31, wid = threadIdx.x >> 5;
    #pragma unroll
    for (int o = 16; o > 0; o >>= 1) acc += __shfl_down_sync(0xffffffffu, acc, o);
    if (lane == 0) sm[wid] = acc;
    __syncthreads();
    if (wid == 0) {
        acc = (lane < (blockDim.x >> 5)) ? sm[lane] : 0.0f;
        #pragma unroll
        for (int o = 16; o > 0; o >>= 1) acc += __shfl_down_sync(0xffffffffu, acc, o);
        if (lane == 0) atomicAdd(&g_const0, acc);
    }
}

// ---------------------------------------------------------------------------
// Kernel 4: GEMV. grid=(CHUNKS, B/ROWS)=(8,32). Each block: 8 rows x 3125 float4.
// coef chunk read ONCE per block (12.8 MB total L2 traffic instead of 102 MB).
__global__ void k_gemv(const float* __restrict__ x, float* __restrict__ out) {
    const int per = (S_DIM / 4) / CHUNKS;          // 3125
    const int base = blockIdx.x * per;
    const int r0 = blockIdx.y * ROWS;
    const float4* __restrict__ cf = reinterpret_cast<const float4*>(g_coef);

    float acc[ROWS];
    #pragma unroll
    for (int j = 0; j < ROWS; j++) acc[j] = 0.0f;

    for (int i = base + threadIdx.x; i < base + per; i += 256) {
        float4 cv = cf[i];
        #pragma unroll
        for (int j = 0; j < ROWS; j++) {
            float4 xv = reinterpret_cast<const float4*>(x + (size_t)(r0 + j) * S_DIM)[i];
            acc[j] += xv.x * cv.x + xv.y * cv.y + xv.z * cv.z + xv.w * cv.w;
        }
    }

    // per-row block reduction: warp reduce -> shared [ROWS][8 warps] -> 64-thread finish
    __shared__ float sm[ROWS][8];
    int lane = threadIdx.x & 31, wid = threadIdx.x >> 5;
    #pragma unroll
    for (int j = 0; j < ROWS; j++) {
        float v = acc[j];
        #pragma unroll
        for (int o = 16; o > 0; o >>= 1) v += __shfl_down_sync(0xffffffffu, v, o);
        if (lane == 0) sm[j][wid] = v;
    }
    __syncthreads();
    if (threadIdx.x < ROWS * 8) {
        int j = threadIdx.x >> 3, w = threadIdx.x & 7;
        float v = sm[j][w];
        #pragma unroll
        for (int o = 4; o > 0; o >>= 1) v += __shfl_down_sync(0xffffffffu, v, o);
        if (w == 0) {
            if (blockIdx.x == 0) v += g_const0;    // exactly one chunk adds const0
            atomicAdd(&out[r0 + j], v);
        }
    }
}

// ---------------------------------------------------------------------------
extern "C" void kernel_launch(void* const* d_in, const int* in_sizes, int n_in,
                              void* d_out, int out_size) {
    const float* x    = (const float*)d_in[0];
    const int*   snp  = (const int*)  d_in[1];
    const int*   gidx = (const int*)  d_in[2];
    const float* ew   = (const float*)d_in[3];
    const float* gb   = (const float*)d_in[4];
    const float* W1   = (const float*)d_in[5];
    const float* b1   = (const float*)d_in[6];
    const float* W2   = (const float*)d_in[7];
    const float* b2   = (const float*)d_in[8];
    float* out = (float*)d_out;

    k_prep<<<(S_DIM + 255) / 256, 256>>>(out);
    k_build_v<<<dim3((G_DIM + 255) / 256, KT), 256>>>(W1, W2);
    k_scatter<<<SCAT_BLOCKS + C0_BLOCKS, 256>>>(snp, gidx, ew, gb, b1, W2, b2);
    k_gemv<<<dim3(CHUNKS, B_DIM / ROWS), 256>>>(x, out);
}

// round 3
// speedup vs baseline: 1.6250x; 1.1241x over previous
#include <cuda_runtime.h>

#define S_DIM 100000
#define G_DIM 18000
#define H_DIM 256
#define E_DIM 600000
#define B_DIM 256

#define KT      8      // k-tiles in build_v (32 k's each)
#define CHUNKS  25     // gemv chunks along S (25000/25 = 1000 float4 each)
#define ROWS    8      // gemv rows per block
#define SCAT_BLOCKS 586   // ceil(150000/256)
#define C0_BLOCKS   9     // const0 tail blocks (2000 g's each)

__device__ float g_v[G_DIM];
__device__ float g_coef[S_DIM];
__device__ float g_const0;

// ---------------------------------------------------------------------------
// Kernel 1: zero all accumulators (coef, v, const0, out)
__global__ void k_prep(float* __restrict__ out) {
    int i = blockIdx.x * blockDim.x + threadIdx.x;
    if (i < S_DIM) g_coef[i] = 0.0f;
    if (i < G_DIM) g_v[i] = 0.0f;
    if (i < B_DIM) out[i] = 0.0f;
    if (i == 0)    g_const0 = 0.0f;
}

// ---------------------------------------------------------------------------
// Kernel 2: v[g] += sum over 32-k tile of W1[k,g]*W2[k].  grid=(71, KT)
__global__ void k_build_v(const float* __restrict__ W1, const float* __restrict__ W2) {
    __shared__ float w2s[32];
    const int k0 = blockIdx.y * (H_DIM / KT);
    if (threadIdx.x < 32) w2s[threadIdx.x] = W2[k0 + threadIdx.x];
    __syncthreads();
    int g = blockIdx.x * blockDim.x + threadIdx.x;
    if (g >= G_DIM) return;
    float acc = 0.0f;
    #pragma unroll
    for (int k = 0; k < 32; k++)
        acc = fmaf(W1[(size_t)(k0 + k) * G_DIM + g], w2s[k], acc);
    atomicAdd(&g_v[g], acc);
}

// ---------------------------------------------------------------------------
// Kernel 3: edge scatter (4 edges/thread, vectorized) + const0 tail blocks.
__global__ void k_scatter(const int* __restrict__ snp, const int* __restrict__ gidx,
                          const float* __restrict__ ew,
                          const float* __restrict__ gene_bias,
                          const float* __restrict__ b1, const float* __restrict__ W2,
                          const float* __restrict__ b2) {
    if (blockIdx.x < SCAT_BLOCKS) {
        int i4 = blockIdx.x * blockDim.x + threadIdx.x;     // quad index
        if (i4 >= E_DIM / 4) return;
        int4   s4 = reinterpret_cast<const int4*>(snp)[i4];
        int4   g4 = reinterpret_cast<const int4*>(gidx)[i4];
        float4 w4 = reinterpret_cast<const float4*>(ew)[i4];
        float v0 = g_v[g4.x], v1 = g_v[g4.y], v2 = g_v[g4.z], v3 = g_v[g4.w];
        atomicAdd(&g_coef[s4.x], w4.x * v0);
        atomicAdd(&g_coef[s4.y], w4.y * v1);
        atomicAdd(&g_coef[s4.z], w4.z * v2);
        atomicAdd(&g_coef[s4.w], w4.w * v3);
        return;
    }
    // ---- const0 tail ----
    int local = blockIdx.x - SCAT_BLOCKS;                   // 0..8
    int start = local * (G_DIM / C0_BLOCKS);                // 2000 per block
    float acc = 0.0f;
    for (int g = start + threadIdx.x; g < start + G_DIM / C0_BLOCKS; g += blockDim.x)
        acc = fmaf(g_v[g], gene_bias[g], acc);
    if (local == 0) {
        acc = fmaf(W2[threadIdx.x], b1[threadIdx.x], acc);  // blockDim == H_DIM
        if (threadIdx.x == 0) acc += b2[0];
    }
    __shared__ float sm[32];
    int lane = threadIdx.x & 31, wid = threadIdx.x >> 5;
    #pragma unroll
    for (int o = 16; o > 0; o >>= 1) acc += __shfl_down_sync(0xffffffffu, acc, o);
    if (lane == 0) sm[wid] = acc;
    __syncthreads();
    if (wid == 0) {
        acc = (lane < (blockDim.x >> 5)) ? sm[lane] : 0.0f;
        #pragma unroll
        for (int o = 16; o > 0; o >>= 1) acc += __shfl_down_sync(0xffffffffu, acc, o);
        if (lane == 0) atomicAdd(&g_const0, acc);
    }
}

// ---------------------------------------------------------------------------
// Kernel 4: GEMV. grid=(CHUNKS, B/ROWS)=(25,32)=800 blocks.
// Each block: 8 rows x 1000 float4 (exactly 4 unrolled iters per thread).
// coef L2 traffic: 400KB x 32 row-groups = 12.8 MB (invariant in CHUNKS).
__global__ void k_gemv(const float* __restrict__ x, float* __restrict__ out) {
    const int per  = (S_DIM / 4) / CHUNKS;         // 1000
    const int base = blockIdx.x * per;
    const int r0   = blockIdx.y * ROWS;
    const float4* __restrict__ cf = reinterpret_cast<const float4*>(g_coef);

    float acc[ROWS];
    #pragma unroll
    for (int j = 0; j < ROWS; j++) acc[j] = 0.0f;

    // per=1000, 256 threads: iters 0..2 full, iter 3 partial (232 threads)
    #pragma unroll
    for (int it = 0; it < 4; it++) {
        int i = base + it * 256 + threadIdx.x;
        if (it * 256 + threadIdx.x < per) {
            float4 cv = cf[i];
            #pragma unroll
            for (int j = 0; j < ROWS; j++) {
                float4 xv = reinterpret_cast<const float4*>(x + (size_t)(r0 + j) * S_DIM)[i];
                acc[j] += xv.x * cv.x + xv.y * cv.y + xv.z * cv.z + xv.w * cv.w;
            }
        }
    }

    // per-row block reduction: warp reduce -> shared [ROWS][8 warps] -> finish
    __shared__ float sm[ROWS][8];
    int lane = threadIdx.x & 31, wid = threadIdx.x >> 5;
    #pragma unroll
    for (int j = 0; j < ROWS; j++) {
        float v = acc[j];
        #pragma unroll
        for (int o = 16; o > 0; o >>= 1) v += __shfl_down_sync(0xffffffffu, v, o);
        if (lane == 0) sm[j][wid] = v;
    }
    __syncthreads();
    if (threadIdx.x < ROWS * 8) {
        int j = threadIdx.x >> 3, w = threadIdx.x & 7;
        float v = sm[j][w];
        #pragma unroll
        for (int o = 4; o > 0; o >>= 1) v += __shfl_down_sync(0xffffffffu, v, o);
        if (w == 0) {
            if (blockIdx.x == 0) v += g_const0;    // exactly one chunk adds const0
            atomicAdd(&out[r0 + j], v);
        }
    }
}

// ---------------------------------------------------------------------------
extern "C" void kernel_launch(void* const* d_in, const int* in_sizes, int n_in,
                              void* d_out, int out_size) {
    const float* x    = (const float*)d_in[0];
    const int*   snp  = (const int*)  d_in[1];
    const int*   gidx = (const int*)  d_in[2];
    const float* ew   = (const float*)d_in[3];
    const float* gb   = (const float*)d_in[4];
    const float* W1   = (const float*)d_in[5];
    const float* b1   = (const float*)d_in[6];
    const float* W2   = (const float*)d_in[7];
    const float* b2   = (const float*)d_in[8];
    float* out = (float*)d_out;

    k_prep<<<(S_DIM + 255) / 256, 256>>>(out);
    k_build_v<<<dim3((G_DIM + 255) / 256, KT), 256>>>(W1, W2);
    k_scatter<<<SCAT_BLOCKS + C0_BLOCKS, 256>>>(snp, gidx, ew, gb, b1, W2, b2);
    k_gemv<<<dim3(CHUNKS, B_DIM / ROWS), 256>>>(x, out);
}

// round 4
// speedup vs baseline: 1.9044x; 1.1719x over previous
#include <cuda_runtime.h>

#define S_DIM 100000
#define G_DIM 18000
#define H_DIM 256
#define E_DIM 600000
#define B_DIM 256

#define KT      8      // k-tiles in build_v (32 k's each)
#define CHUNKS  50     // gemv chunks along S (25000/50 = 500 float4 each)
#define ROWS    8      // gemv rows per block
#define SCAT_BLOCKS 586   // ceil(150000/256)
#define C0_BLOCKS   9     // const0 tail blocks (2000 g's each)

__device__ float g_v[G_DIM];
__device__ float g_coef[S_DIM];
__device__ float g_const0;

// ---------------------------------------------------------------------------
// Kernel 1 (tiny): zero g_v, out, const0. (coef zeroed inside k_build_v.)
__global__ void k_prep(float* __restrict__ out) {
    int i = blockIdx.x * blockDim.x + threadIdx.x;   // 72*256 = 18432
    if (i < G_DIM) g_v[i] = 0.0f;
    if (i < B_DIM) out[i] = 0.0f;
    if (i == 0)    g_const0 = 0.0f;
}

// ---------------------------------------------------------------------------
// Kernel 2: grid=(71, KT+1).
//   y <  KT : v[g] += sum over 32-k tile of W1[k,g]*W2[k]
//   y == KT : zero coef (stream order puts this before k_scatter's atomics)
__global__ void k_build_v(const float* __restrict__ W1, const float* __restrict__ W2) {
    if (blockIdx.y == KT) {
        int i = blockIdx.x * blockDim.x + threadIdx.x;   // 0..18175
        float4 z = make_float4(0.f, 0.f, 0.f, 0.f);
        float4* c4 = reinterpret_cast<float4*>(g_coef);
        if (i < S_DIM / 4) c4[i] = z;
        int j = i + 18176;
        if (j < S_DIM / 4) c4[j] = z;
        return;
    }
    __shared__ float w2s[32];
    const int k0 = blockIdx.y * (H_DIM / KT);
    if (threadIdx.x < 32) w2s[threadIdx.x] = W2[k0 + threadIdx.x];
    __syncthreads();
    int g = blockIdx.x * blockDim.x + threadIdx.x;
    if (g >= G_DIM) return;
    float acc = 0.0f;
    #pragma unroll
    for (int k = 0; k < 32; k++)
        acc = fmaf(W1[(size_t)(k0 + k) * G_DIM + g], w2s[k], acc);
    atomicAdd(&g_v[g], acc);
}

// ---------------------------------------------------------------------------
// Kernel 3: edge scatter (4 edges/thread, vectorized) + const0 tail blocks.
__global__ void k_scatter(const int* __restrict__ snp, const int* __restrict__ gidx,
                          const float* __restrict__ ew,
                          const float* __restrict__ gene_bias,
                          const float* __restrict__ b1, const float* __restrict__ W2,
                          const float* __restrict__ b2) {
    if (blockIdx.x < SCAT_BLOCKS) {
        int i4 = blockIdx.x * blockDim.x + threadIdx.x;     // quad index
        if (i4 >= E_DIM / 4) return;
        int4   s4 = reinterpret_cast<const int4*>(snp)[i4];
        int4   g4 = reinterpret_cast<const int4*>(gidx)[i4];
        float4 w4 = reinterpret_cast<const float4*>(ew)[i4];
        float v0 = g_v[g4.x], v1 = g_v[g4.y], v2 = g_v[g4.z], v3 = g_v[g4.w];
        atomicAdd(&g_coef[s4.x], w4.x * v0);
        atomicAdd(&g_coef[s4.y], w4.y * v1);
        atomicAdd(&g_coef[s4.z], w4.z * v2);
        atomicAdd(&g_coef[s4.w], w4.w * v3);
        return;
    }
    // ---- const0 tail ----
    int local = blockIdx.x - SCAT_BLOCKS;                   // 0..8
    int start = local * (G_DIM / C0_BLOCKS);                // 2000 per block
    float acc = 0.0f;
    for (int g = start + threadIdx.x; g < start + G_DIM / C0_BLOCKS; g += blockDim.x)
        acc = fmaf(g_v[g], gene_bias[g], acc);
    if (local == 0) {
        acc = fmaf(W2[threadIdx.x], b1[threadIdx.x], acc);  // blockDim == H_DIM
        if (threadIdx.x == 0) acc += b2[0];
    }
    __shared__ float sm[32];
    int lane = threadIdx.x & 31, wid = threadIdx.x >> 5;
    #pragma unroll
    for (int o = 16; o > 0; o >>= 1) acc += __shfl_down_sync(0xffffffffu, acc, o);
    if (lane == 0) sm[wid] = acc;
    __syncthreads();
    if (wid == 0) {
        acc = (lane < (blockDim.x >> 5)) ? sm[lane] : 0.0f;
        #pragma unroll
        for (int o = 16; o > 0; o >>= 1) acc += __shfl_down_sync(0xffffffffu, acc, o);
        if (lane == 0) atomicAdd(&g_const0, acc);
    }
}

// ---------------------------------------------------------------------------
// Kernel 4: GEMV. grid=(CHUNKS, B/ROWS)=(50,32)=1600 blocks.
// Each block: 8 rows x 500 float4. x loads streamed (__ldcs, evict-first:
// zero reuse), coef via __ldg (stays L2/L1-resident; 12.8 MB total L2 reuse).
__global__ void __launch_bounds__(256, 6)
k_gemv(const float* __restrict__ x, float* __restrict__ out) {
    const int per  = (S_DIM / 4) / CHUNKS;         // 500
    const int base = blockIdx.x * per;
    const int r0   = blockIdx.y * ROWS;
    const float4* __restrict__ cf = reinterpret_cast<const float4*>(g_coef);

    float acc[ROWS];
    #pragma unroll
    for (int j = 0; j < ROWS; j++) acc[j] = 0.0f;

    // per=500, 256 threads: iter 0 full, iter 1 partial (244 threads)
    #pragma unroll
    for (int it = 0; it < 2; it++) {
        int off = it * 256 + threadIdx.x;
        if (off < per) {
            int i = base + off;
            float4 cv = __ldg(&cf[i]);
            #pragma unroll
            for (int j = 0; j < ROWS; j++) {
                float4 xv = __ldcs(reinterpret_cast<const float4*>(
                                x + (size_t)(r0 + j) * S_DIM) + i);
                acc[j] += xv.x * cv.x + xv.y * cv.y + xv.z * cv.z + xv.w * cv.w;
            }
        }
    }

    // per-row block reduction: warp reduce -> shared [ROWS][8 warps] -> finish
    __shared__ float sm[ROWS][8];
    int lane = threadIdx.x & 31, wid = threadIdx.x >> 5;
    #pragma unroll
    for (int j = 0; j < ROWS; j++) {
        float v = acc[j];
        #pragma unroll
        for (int o = 16; o > 0; o >>= 1) v += __shfl_down_sync(0xffffffffu, v, o);
        if (lane == 0) sm[j][wid] = v;
    }
    __syncthreads();
    if (threadIdx.x < ROWS * 8) {
        int j = threadIdx.x >> 3, w = threadIdx.x & 7;
        float v = sm[j][w];
        #pragma unroll
        for (int o = 4; o > 0; o >>= 1) v += __shfl_down_sync(0xffffffffu, v, o);
        if (w == 0) {
            if (blockIdx.x == 0) v += g_const0;    // exactly one chunk adds const0
            atomicAdd(&out[r0 + j], v);
        }
    }
}

// ---------------------------------------------------------------------------
extern "C" void kernel_launch(void* const* d_in, const int* in_sizes, int n_in,
                              void* d_out, int out_size) {
    const float* x    = (const float*)d_in[0];
    const int*   snp  = (const int*)  d_in[1];
    const int*   gidx = (const int*)  d_in[2];
    const float* ew   = (const float*)d_in[3];
    const float* gb   = (const float*)d_in[4];
    const float* W1   = (const float*)d_in[5];
    const float* b1   = (const float*)d_in[6];
    const float* W2   = (const float*)d_in[7];
    const float* b2   = (const float*)d_in[8];
    float* out = (float*)d_out;

    k_prep<<<72, 256>>>(out);
    k_build_v<<<dim3(71, KT + 1), 256>>>(W1, W2);
    k_scatter<<<SCAT_BLOCKS + C0_BLOCKS, 256>>>(snp, gidx, ew, gb, b1, W2, b2);
    k_gemv<<<dim3(CHUNKS, B_DIM / ROWS), 256>>>(x, out);
}